// round 14
// baseline (speedup 1.0000x reference)
#include <cuda_runtime.h>
#include <cuda_fp16.h>
#include <stdint.h>

// ---------------------------------------------------------------------------
// Pure fp16 GEMMs (fp32 accum) on mma.sync. R14 = R13 mainloop, with:
//  - GEMM2 tile 128x96 (2048 CTAs = 6.92 waves, kills the 15.6% tail loss
//    of the 5.19-wave 128x128 grid; acc 48 regs -> less pressure)
//  - all prep fused into ONE kernel launch.
// GEMM1 unchanged (CTA 128x128, 20.8 waves, tail negligible).
// Both: 256 thr, 2 CTAs/SM, Kc=64 (two 32-col sub-blocks), 3-stage cp.async,
// one barrier/chunk, hardware tanh.approx GELU.
// ---------------------------------------------------------------------------

#define S1_STAGE 32768             // A[2][128][64B] | B[2][128][64B]
#define S1_TOTAL (3 * S1_STAGE)    // 96 KB
#define S2_STAGE 28672             // A[2][128][64B] | B[2][96][64B]
#define S2_TOTAL (3 * S2_STAGE)    // 84 KB

// ---------------- static device scratch (no allocations allowed) -----------
static __device__ __align__(16) __half g_Xh [(size_t)32768 * 768];
static __device__ __align__(16) __half g_W1t[(size_t)3072 * 768];     // [N][K]
static __device__ __align__(16) __half g_W2t[(size_t)576 * 3072];     // [N][K]
static __device__ __align__(16) __half g_Wet[(size_t)6 * 192 * 3072];
static __device__ __align__(16) __half g_Hf [(size_t)32768 * 3072];

// ---------------- PTX helpers ----------------------------------------------
__device__ __forceinline__ uint32_t smem_u32(const void* p) {
    uint32_t a;
    asm("{ .reg .u64 t; cvta.to.shared.u64 t, %1; cvt.u32.u64 %0, t; }" : "=r"(a) : "l"(p));
    return a;
}
__device__ __forceinline__ void cp16(uint32_t saddr, const void* g) {
    asm volatile("cp.async.cg.shared.global [%0], [%1], 16;" :: "r"(saddr), "l"(g));
}
#define CP_COMMIT() asm volatile("cp.async.commit_group;" ::: "memory")
#define CP_WAIT(n)  asm volatile("cp.async.wait_group " #n ";" ::: "memory")

__device__ __forceinline__ void ldsm4(uint32_t* r, uint32_t addr) {
    asm volatile("ldmatrix.sync.aligned.m8n8.x4.shared.b16 {%0,%1,%2,%3}, [%4];"
        : "=r"(r[0]), "=r"(r[1]), "=r"(r[2]), "=r"(r[3]) : "r"(addr));
}
__device__ __forceinline__ void mma_f16(float* c, const uint32_t* a,
                                        uint32_t b0, uint32_t b1) {
    asm volatile("mma.sync.aligned.m16n8k16.row.col.f32.f16.f16.f32 "
        "{%0,%1,%2,%3}, {%4,%5,%6,%7}, {%8,%9}, {%0,%1,%2,%3};"
        : "+f"(c[0]), "+f"(c[1]), "+f"(c[2]), "+f"(c[3])
        : "r"(a[0]), "r"(a[1]), "r"(a[2]), "r"(a[3]), "r"(b0), "r"(b1));
}

// gelu via hardware tanh.approx.f32 (single MUFU op)
__device__ __forceinline__ float gelu_fast(float x) {
    float u = 0.7978845608028654f * x * fmaf(0.044715f * x, x, 1.0f);
    float t;
    asm("tanh.approx.f32 %0, %1;" : "=f"(t) : "f"(u));
    return 0.5f * x * (1.0f + t);
}
// int64-vs-int32 robust expert index (values in [0,6) -> int64 odd words all 0)
__device__ __forceinline__ int load_expert_index(const int* __restrict__ idx32, int b) {
    int odd_or = 0;
    #pragma unroll
    for (int j = 1; j < 32; j += 2) odd_or |= idx32[j];
    return (odd_or == 0) ? idx32[2 * b] : idx32[b];
}

// ---------------------------------------------------------------------------
// Fused prep: one launch. Region-decoded 1D grid of 256-thread blocks.
//  [0, 24576)            : X fp32 -> fp16 (4 elems/thread)
//  [24576, +2304)        : W1 transpose  (R=768,  C=3072)
//  [.., +1728)           : W2 transpose  (R=3072, C=576)
//  [.., +3456)           : We transpose  (R=3072, C=192, 6 experts)
// ---------------------------------------------------------------------------
__global__ void k_prep(const float* __restrict__ X, const float* __restrict__ W1,
                       const float* __restrict__ W2, const float* __restrict__ We)
{
    const int b = blockIdx.x;
    const int tid = threadIdx.x;
    if (b < 24576) {
        size_t i = ((size_t)b * 256 + tid) * 4;
        float4 v = *(const float4*)(X + i);
        __half2 a = __floats2half2_rn(v.x, v.y);
        __half2 c = __floats2half2_rn(v.z, v.w);
        uint2 o;
        o.x = *reinterpret_cast<uint32_t*>(&a);
        o.y = *reinterpret_cast<uint32_t*>(&c);
        *(uint2*)(g_Xh + i) = o;
        return;
    }
    const float* src; __half* dst; int R, C, bx, by;
    int t = b - 24576;
    if (t < 2304)            { src = W1; dst = g_W1t; R = 768;  C = 3072; bx = t % 96; by = t / 96; }
    else if ((t -= 2304) < 1728) { src = W2; dst = g_W2t; R = 3072; C = 576;  bx = t % 18; by = t / 18; }
    else {
        t -= 1728;
        int z = t / 576, r = t % 576;
        src = We + (size_t)z * 3072 * 192;
        dst = g_Wet + (size_t)z * 192 * 3072;
        R = 3072; C = 192; bx = r % 6; by = r / 6;
    }
    __shared__ float tsh[32][33];
    int tx = tid & 31, ty = tid >> 5;  // (32, 8)
    int bx32 = bx * 32, by32 = by * 32;
    #pragma unroll
    for (int i = 0; i < 32; i += 8)
        tsh[ty + i][tx] = src[(size_t)(by32 + ty + i) * C + bx32 + tx];
    __syncthreads();
    #pragma unroll
    for (int i = 0; i < 32; i += 8)
        dst[(size_t)(bx32 + ty + i) * R + (by32 + tx)] = __float2half_rn(tsh[tx][ty + i]);
}

// ---------------------------------------------------------------------------
// GEMM1: H = gelu(X @ W1 + b1).  CTA 128x128, grid (24, 256), NC = 12.
// Stage: A0 +0, A1 +8192, B0 +16384, B1 +24576 (each 128 rows x 64 B,
// swizzle p = ch ^ ((r>>1)&3)).
// ---------------------------------------------------------------------------
struct Frags1 { float acc[2][8][4]; };

__device__ __forceinline__ void compute1(uint32_t base, int st, int lane,
                                         int wm, int wn, Frags1& F)
{
    const uint32_t Ab = base + st;
    const uint32_t Bb = base + st + 16384;
    const int m8 = lane >> 3, l7 = lane & 7;
    #pragma unroll
    for (int ks = 0; ks < 4; ks++) {
        const uint32_t Asub = Ab + (ks >> 1) * 8192;
        const uint32_t Bsub = Bb + (ks >> 1) * 8192;
        const int kk = ks & 1;
        uint32_t a[2][4];
        #pragma unroll
        for (int mi = 0; mi < 2; mi++) {
            int rr = wm * 32 + mi * 16 + (m8 & 1) * 8 + l7;
            int ch = kk * 2 + (m8 >> 1);
            int p = ch ^ ((rr >> 1) & 3);
            ldsm4(a[mi], Asub + (uint32_t)(rr * 64 + p * 16));
        }
        #pragma unroll
        for (int jp = 0; jp < 4; jp++) {
            int nrow = wn * 64 + jp * 16 + (m8 >> 1) * 8 + l7;
            int ch = kk * 2 + (m8 & 1);
            int p = ch ^ ((nrow >> 1) & 3);
            uint32_t tb[4];
            ldsm4(tb, Bsub + (uint32_t)(nrow * 64 + p * 16));
            #pragma unroll
            for (int mi = 0; mi < 2; mi++) {
                mma_f16(F.acc[mi][2 * jp],     a[mi], tb[0], tb[1]);
                mma_f16(F.acc[mi][2 * jp + 1], a[mi], tb[2], tb[3]);
            }
        }
    }
}

__global__ void __launch_bounds__(256, 2)
k_mm1(const float* __restrict__ b1)
{
    extern __shared__ char smem[];
    const uint32_t base = smem_u32(smem);
    const int tid = threadIdx.x, wid = tid >> 5, lane = tid & 31;
    const int bx = blockIdx.x, by = blockIdx.y;
    const int K = 768, NC = 12;
    const int wm = wid & 3, wn = wid >> 2;

    auto issue = [&](int c) {
        int st = (c % 3) * S1_STAGE;
        #pragma unroll
        for (int t = 0; t < 8; t++) {
            int idx = tid + t * 256;           // 0..2047
            int region = idx >> 9;             // 0: A0, 1: A1, 2: B0, 3: B1
            int w = idx & 511, r = w >> 2, ch = w & 3;
            int sub = region & 1;
            int isB = region >> 1;
            int p = ch ^ ((r >> 1) & 3);
            uint32_t sa = base + st + isB * 16384 + sub * 8192 + r * 64 + p * 16;
            const __half* src;
            size_t grow;
            if (!isB) { src = g_Xh;  grow = (size_t)(by * 128 + r) * K; }
            else      { src = g_W1t; grow = (size_t)(bx * 128 + r) * K; }
            cp16(sa, src + grow + c * 64 + sub * 32 + ch * 8);
        }
        CP_COMMIT();
    };

    Frags1 F;
    #pragma unroll
    for (int mi = 0; mi < 2; mi++)
        #pragma unroll
        for (int nj = 0; nj < 8; nj++)
            #pragma unroll
            for (int q = 0; q < 4; q++) F.acc[mi][nj][q] = 0.0f;

    issue(0); issue(1);
    for (int c = 0; c < NC; c++) {
        CP_WAIT(1);
        __syncthreads();
        if (c + 2 < NC) issue(c + 2); else CP_COMMIT();
        compute1(base, (c % 3) * S1_STAGE, lane, wm, wn, F);
    }

    // epilogue: bias + fast GELU -> fp16 into H
    const int g = lane >> 2, t4 = lane & 3;
    #pragma unroll
    for (int mi = 0; mi < 2; mi++) {
        #pragma unroll
        for (int nj = 0; nj < 8; nj++) {
            int row0 = by * 128 + wm * 32 + mi * 16 + g;
            int col  = bx * 128 + wn * 64 + nj * 8 + 2 * t4;
            float2 bb = *(const float2*)(b1 + col);
            float x0 = gelu_fast(F.acc[mi][nj][0] + bb.x);
            float x1 = gelu_fast(F.acc[mi][nj][1] + bb.y);
            float x2 = gelu_fast(F.acc[mi][nj][2] + bb.x);
            float x3 = gelu_fast(F.acc[mi][nj][3] + bb.y);
            __half2 h01 = __floats2half2_rn(x0, x1);
            __half2 h23 = __floats2half2_rn(x2, x3);
            *(uint32_t*)(g_Hf + (size_t)row0 * 3072 + col) =
                *reinterpret_cast<uint32_t*>(&h01);
            *(uint32_t*)(g_Hf + (size_t)(row0 + 8) * 3072 + col) =
                *reinterpret_cast<uint32_t*>(&h23);
        }
    }
}

// ---------------------------------------------------------------------------
// GEMM2: out = H @ [W2 | We[idx]] + [b2 | be[idx]].  CTA 128x96,
// grid (8, 256) = 2048 CTAs = 6.92 waves (tail loss ~1%). NC = 48.
// Stage: A0 +0, A1 +8192, B0 +16384, B1 +22528 (B sub = 96 rows x 64 B).
// Warp tile 32x48 (nj = 6), acc 48 regs.
// ---------------------------------------------------------------------------
struct Frags2 { float acc[2][6][4]; };

__device__ __forceinline__ void compute2(uint32_t base, int st, int lane,
                                         int wm, int wn, Frags2& F)
{
    const uint32_t Ab = base + st;
    const uint32_t Bb = base + st + 16384;
    const int m8 = lane >> 3, l7 = lane & 7;
    #pragma unroll
    for (int ks = 0; ks < 4; ks++) {
        const uint32_t Asub = Ab + (ks >> 1) * 8192;
        const uint32_t Bsub = Bb + (ks >> 1) * 6144;
        const int kk = ks & 1;
        uint32_t a[2][4];
        #pragma unroll
        for (int mi = 0; mi < 2; mi++) {
            int rr = wm * 32 + mi * 16 + (m8 & 1) * 8 + l7;
            int ch = kk * 2 + (m8 >> 1);
            int p = ch ^ ((rr >> 1) & 3);
            ldsm4(a[mi], Asub + (uint32_t)(rr * 64 + p * 16));
        }
        #pragma unroll
        for (int jp = 0; jp < 3; jp++) {
            int nrow = wn * 48 + jp * 16 + (m8 >> 1) * 8 + l7;
            int ch = kk * 2 + (m8 & 1);
            int p = ch ^ ((nrow >> 1) & 3);
            uint32_t tb[4];
            ldsm4(tb, Bsub + (uint32_t)(nrow * 64 + p * 16));
            #pragma unroll
            for (int mi = 0; mi < 2; mi++) {
                mma_f16(F.acc[mi][2 * jp],     a[mi], tb[0], tb[1]);
                mma_f16(F.acc[mi][2 * jp + 1], a[mi], tb[2], tb[3]);
            }
        }
    }
}

__global__ void __launch_bounds__(256, 2)
k_mm2(const float* __restrict__ b2, const float* __restrict__ be,
      const int* __restrict__ idx32, float* __restrict__ out)
{
    extern __shared__ char smem[];
    const uint32_t base = smem_u32(smem);
    const int tid = threadIdx.x, wid = tid >> 5, lane = tid & 31;
    const int bx = blockIdx.x, by = blockIdx.y;
    const int K = 3072, NC = 48;
    const int wm = wid & 3, wn = wid >> 2;
    const int e = load_expert_index(idx32, by >> 3);

    auto issue = [&](int c) {
        int st = (c % 3) * S2_STAGE;
        #pragma unroll
        for (int t = 0; t < 7; t++) {
            int idx = tid + t * 256;           // 0..1791
            const __half* src;
            size_t grow;
            uint32_t off;
            int r, ch;
            if (idx < 1024) {
                int sub = idx >> 9, w = idx & 511;
                r = w >> 2; ch = w & 3;
                off = sub * 8192;
                src = g_Hf;
                grow = (size_t)(by * 128 + r) * K + c * 64 + sub * 32;
            } else {
                int j = idx - 1024;
                int sub = (j >= 384) ? 1 : 0;
                int w = j - sub * 384;
                r = w >> 2; ch = w & 3;
                off = 16384 + sub * 6144;
                int n = bx * 96 + r;
                if (n < 576) { src = g_W2t; grow = (size_t)n * K; }
                else { src = g_Wet; grow = ((size_t)e * 192 + (n - 576)) * K; }
                grow += c * 64 + sub * 32;
            }
            int p = ch ^ ((r >> 1) & 3);
            uint32_t sa = base + st + off + r * 64 + p * 16;
            cp16(sa, src + grow + ch * 8);
        }
        CP_COMMIT();
    };

    Frags2 F;
    #pragma unroll
    for (int mi = 0; mi < 2; mi++)
        #pragma unroll
        for (int nj = 0; nj < 6; nj++)
            #pragma unroll
            for (int q = 0; q < 4; q++) F.acc[mi][nj][q] = 0.0f;

    issue(0); issue(1);
    for (int c = 0; c < NC; c++) {
        CP_WAIT(1);
        __syncthreads();
        if (c + 2 < NC) issue(c + 2); else CP_COMMIT();
        compute2(base, (c % 3) * S2_STAGE, lane, wm, wn, F);
    }

    // epilogue: + bias (shared / expert), fp32 out [32768][768]
    const int g = lane >> 2, t4 = lane & 3;
    #pragma unroll
    for (int mi = 0; mi < 2; mi++) {
        #pragma unroll
        for (int nj = 0; nj < 6; nj++) {
            int row0 = by * 128 + wm * 32 + mi * 16 + g;
            int col  = bx * 96 + wn * 48 + nj * 8 + 2 * t4;
            float bx0, bx1;
            if (col < 576) { float2 bb = *(const float2*)(b2 + col); bx0 = bb.x; bx1 = bb.y; }
            else { float2 bb = *(const float2*)(be + e * 192 + (col - 576)); bx0 = bb.x; bx1 = bb.y; }
            float2 v0 = make_float2(F.acc[mi][nj][0] + bx0, F.acc[mi][nj][1] + bx1);
            float2 v1 = make_float2(F.acc[mi][nj][2] + bx0, F.acc[mi][nj][3] + bx1);
            *(float2*)(out + (size_t)row0 * 768 + col) = v0;
            *(float2*)(out + (size_t)(row0 + 8) * 768 + col) = v1;
        }
    }
}

// ---------------------------------------------------------------------------
extern "C" void kernel_launch(void* const* d_in, const int* in_sizes, int n_in,
                              void* d_out, int out_size)
{
    (void)in_sizes; (void)n_in; (void)out_size;
    const float* X   = (const float*)d_in[0];
    const int*   idx = (const int*)d_in[1];
    const float* W1  = (const float*)d_in[2];
    const float* b1  = (const float*)d_in[3];
    const float* W2  = (const float*)d_in[4];
    const float* b2  = (const float*)d_in[5];
    const float* We  = (const float*)d_in[6];
    const float* be  = (const float*)d_in[7];
    float* out = (float*)d_out;

    cudaFuncSetAttribute(k_mm1, cudaFuncAttributeMaxDynamicSharedMemorySize, S1_TOTAL);
    cudaFuncSetAttribute(k_mm2, cudaFuncAttributeMaxDynamicSharedMemorySize, S2_TOTAL);

    // fused prep: X convert + W1/W2/We transposes in one launch
    k_prep<<<24576 + 2304 + 1728 + 3456, 256>>>(X, W1, W2, We);

    k_mm1<<<dim3(3072 / 128, 32768 / 128), 256, S1_TOTAL>>>(b1);
    k_mm2<<<dim3(768 / 96, 32768 / 128), 256, S2_TOTAL>>>(b2, be, idx, out);
}

// round 15
// speedup vs baseline: 1.0213x; 1.0213x over previous
#include <cuda_runtime.h>
#include <cuda_fp16.h>
#include <stdint.h>

// ---------------------------------------------------------------------------
// Pure fp16 GEMMs (fp32 accum) on mma.sync. R15 = R13's GEMM kernels exactly
// (CTA 128x128, 256 thr, 2 CTAs/SM, Kc=64 two 32-col sub-blocks, 3-stage
// cp.async, one barrier/chunk, hardware tanh.approx GELU) + R14's fused
// single-launch prep (measured 33.6us, numerics-identical).
// R14's 128x96 GEMM2 tile reverted: SMEM-redundancy cost beat the wave-tail
// win on the co-bound mainloop.
// ---------------------------------------------------------------------------

#define STAGE_BYTES 32768          // A[2][128][64B] 16K | B[2][128][64B] 16K
#define NSTAGES 3
#define SMEM_TOTAL (NSTAGES * STAGE_BYTES)   // 96 KB -> 2 CTAs/SM

// ---------------- static device scratch (no allocations allowed) -----------
static __device__ __align__(16) __half g_Xh [(size_t)32768 * 768];
static __device__ __align__(16) __half g_W1t[(size_t)3072 * 768];     // [N][K]
static __device__ __align__(16) __half g_W2t[(size_t)576 * 3072];     // [N][K]
static __device__ __align__(16) __half g_Wet[(size_t)6 * 192 * 3072];
static __device__ __align__(16) __half g_Hf [(size_t)32768 * 3072];

// ---------------- PTX helpers ----------------------------------------------
__device__ __forceinline__ uint32_t smem_u32(const void* p) {
    uint32_t a;
    asm("{ .reg .u64 t; cvta.to.shared.u64 t, %1; cvt.u32.u64 %0, t; }" : "=r"(a) : "l"(p));
    return a;
}
__device__ __forceinline__ void cp16(uint32_t saddr, const void* g) {
    asm volatile("cp.async.cg.shared.global [%0], [%1], 16;" :: "r"(saddr), "l"(g));
}
#define CP_COMMIT() asm volatile("cp.async.commit_group;" ::: "memory")
#define CP_WAIT(n)  asm volatile("cp.async.wait_group " #n ";" ::: "memory")

__device__ __forceinline__ void ldsm4(uint32_t* r, uint32_t addr) {
    asm volatile("ldmatrix.sync.aligned.m8n8.x4.shared.b16 {%0,%1,%2,%3}, [%4];"
        : "=r"(r[0]), "=r"(r[1]), "=r"(r[2]), "=r"(r[3]) : "r"(addr));
}
__device__ __forceinline__ void mma_f16(float* c, const uint32_t* a,
                                        uint32_t b0, uint32_t b1) {
    asm volatile("mma.sync.aligned.m16n8k16.row.col.f32.f16.f16.f32 "
        "{%0,%1,%2,%3}, {%4,%5,%6,%7}, {%8,%9}, {%0,%1,%2,%3};"
        : "+f"(c[0]), "+f"(c[1]), "+f"(c[2]), "+f"(c[3])
        : "r"(a[0]), "r"(a[1]), "r"(a[2]), "r"(a[3]), "r"(b0), "r"(b1));
}

// gelu via hardware tanh.approx.f32 (single MUFU op)
__device__ __forceinline__ float gelu_fast(float x) {
    float u = 0.7978845608028654f * x * fmaf(0.044715f * x, x, 1.0f);
    float t;
    asm("tanh.approx.f32 %0, %1;" : "=f"(t) : "f"(u));
    return 0.5f * x * (1.0f + t);
}
// int64-vs-int32 robust expert index (values in [0,6) -> int64 odd words all 0)
__device__ __forceinline__ int load_expert_index(const int* __restrict__ idx32, int b) {
    int odd_or = 0;
    #pragma unroll
    for (int j = 1; j < 32; j += 2) odd_or |= idx32[j];
    return (odd_or == 0) ? idx32[2 * b] : idx32[b];
}

// ---------------------------------------------------------------------------
// Fused prep: one launch. Region-decoded 1D grid of 256-thread blocks.
//  [0, 24576)     : X fp32 -> fp16 (4 elems/thread)
//  [24576, +2304) : W1 transpose (R=768,  C=3072)
//  [.., +1728)    : W2 transpose (R=3072, C=576)
//  [.., +3456)    : We transpose (R=3072, C=192, 6 experts)
// ---------------------------------------------------------------------------
__global__ void k_prep(const float* __restrict__ X, const float* __restrict__ W1,
                       const float* __restrict__ W2, const float* __restrict__ We)
{
    const int b = blockIdx.x;
    const int tid = threadIdx.x;
    if (b < 24576) {
        size_t i = ((size_t)b * 256 + tid) * 4;
        float4 v = *(const float4*)(X + i);
        __half2 a = __floats2half2_rn(v.x, v.y);
        __half2 c = __floats2half2_rn(v.z, v.w);
        uint2 o;
        o.x = *reinterpret_cast<uint32_t*>(&a);
        o.y = *reinterpret_cast<uint32_t*>(&c);
        *(uint2*)(g_Xh + i) = o;
        return;
    }
    const float* src; __half* dst; int R, C, bx, by;
    int t = b - 24576;
    if (t < 2304)                { src = W1; dst = g_W1t; R = 768;  C = 3072; bx = t % 96; by = t / 96; }
    else if ((t -= 2304) < 1728) { src = W2; dst = g_W2t; R = 3072; C = 576;  bx = t % 18; by = t / 18; }
    else {
        t -= 1728;
        int z = t / 576, r = t % 576;
        src = We + (size_t)z * 3072 * 192;
        dst = g_Wet + (size_t)z * 192 * 3072;
        R = 3072; C = 192; bx = r % 6; by = r / 6;
    }
    __shared__ float tsh[32][33];
    int tx = tid & 31, ty = tid >> 5;  // (32, 8)
    int bx32 = bx * 32, by32 = by * 32;
    #pragma unroll
    for (int i = 0; i < 32; i += 8)
        tsh[ty + i][tx] = src[(size_t)(by32 + ty + i) * C + bx32 + tx];
    __syncthreads();
    #pragma unroll
    for (int i = 0; i < 32; i += 8)
        dst[(size_t)(bx32 + ty + i) * R + (by32 + tx)] = __float2half_rn(tsh[tx][ty + i]);
}

// ---------------------------------------------------------------------------
// Mainloop compute: chunk = 64 K-columns as two 32-col sub-blocks.
// Stage layout: A sub0 +0, A sub1 +8192, B sub0 +16384, B sub1 +24576.
// Each sub-block: 128 rows x 64 B, 16B-chunk swizzle p = ch ^ ((r>>1)&3).
// ---------------------------------------------------------------------------

struct Frags {
    float acc[2][8][4];
};

__device__ __forceinline__ void compute_chunk(uint32_t base, int st, int lane,
                                              int wm, int wn, Frags& F)
{
    const uint32_t Ab = base + st;
    const uint32_t Bb = base + st + 16384;
    const int m8 = lane >> 3, l7 = lane & 7;
    #pragma unroll
    for (int ks = 0; ks < 4; ks++) {
        const uint32_t Asub = Ab + (ks >> 1) * 8192;
        const uint32_t Bsub = Bb + (ks >> 1) * 8192;
        const int kk = ks & 1;
        uint32_t a[2][4];
        #pragma unroll
        for (int mi = 0; mi < 2; mi++) {
            int rr = wm * 32 + mi * 16 + (m8 & 1) * 8 + l7;
            int ch = kk * 2 + (m8 >> 1);
            int p = ch ^ ((rr >> 1) & 3);
            ldsm4(a[mi], Asub + (uint32_t)(rr * 64 + p * 16));
        }
        #pragma unroll
        for (int jp = 0; jp < 4; jp++) {
            int nrow = wn * 64 + jp * 16 + (m8 >> 1) * 8 + l7;
            int ch = kk * 2 + (m8 & 1);
            int p = ch ^ ((nrow >> 1) & 3);
            uint32_t tb[4];
            ldsm4(tb, Bsub + (uint32_t)(nrow * 64 + p * 16));
            #pragma unroll
            for (int mi = 0; mi < 2; mi++) {
                mma_f16(F.acc[mi][2 * jp],     a[mi], tb[0], tb[1]);
                mma_f16(F.acc[mi][2 * jp + 1], a[mi], tb[2], tb[3]);
            }
        }
    }
}

// ---------------------------------------------------------------------------
// GEMM1: H = gelu(X @ W1 + b1).  A = Xh [32768][768], B = W1t [3072][768]
// Grid (24, 256), 256 threads, 2 CTAs/SM.  NC = 768/64 = 12.
// ---------------------------------------------------------------------------
__global__ void __launch_bounds__(256, 2)
k_mm1(const float* __restrict__ b1)
{
    extern __shared__ char smem[];
    const uint32_t base = smem_u32(smem);
    const int tid = threadIdx.x, wid = tid >> 5, lane = tid & 31;
    const int bx = blockIdx.x, by = blockIdx.y;
    const int K = 768, NC = 12;
    const int wm = wid & 3, wn = wid >> 2;

    auto issue = [&](int c) {
        int st = (c % NSTAGES) * STAGE_BYTES;
        #pragma unroll
        for (int t = 0; t < 8; t++) {
            int idx = tid + t * 256;           // 0..2047
            int region = idx >> 9;             // 0: A0, 1: A1, 2: B0, 3: B1
            int w = idx & 511, r = w >> 2, ch = w & 3;
            int sub = region & 1;
            int isB = region >> 1;
            int p = ch ^ ((r >> 1) & 3);
            uint32_t sa = base + st + isB * 16384 + sub * 8192 + r * 64 + p * 16;
            const __half* src;
            size_t grow;
            if (!isB) { src = g_Xh;  grow = (size_t)(by * 128 + r) * K; }
            else      { src = g_W1t; grow = (size_t)(bx * 128 + r) * K; }
            cp16(sa, src + grow + c * 64 + sub * 32 + ch * 8);
        }
        CP_COMMIT();
    };

    Frags F;
    #pragma unroll
    for (int mi = 0; mi < 2; mi++)
        #pragma unroll
        for (int nj = 0; nj < 8; nj++)
            #pragma unroll
            for (int q = 0; q < 4; q++) F.acc[mi][nj][q] = 0.0f;

    issue(0); issue(1);
    for (int c = 0; c < NC; c++) {
        CP_WAIT(1);
        __syncthreads();
        if (c + 2 < NC) issue(c + 2); else CP_COMMIT();
        compute_chunk(base, (c % NSTAGES) * STAGE_BYTES, lane, wm, wn, F);
    }

    // epilogue: bias + fast GELU -> fp16 into H
    const int g = lane >> 2, t4 = lane & 3;
    #pragma unroll
    for (int mi = 0; mi < 2; mi++) {
        #pragma unroll
        for (int nj = 0; nj < 8; nj++) {
            int row0 = by * 128 + wm * 32 + mi * 16 + g;
            int col  = bx * 128 + wn * 64 + nj * 8 + 2 * t4;
            float2 bb = *(const float2*)(b1 + col);
            float x0 = gelu_fast(F.acc[mi][nj][0] + bb.x);
            float x1 = gelu_fast(F.acc[mi][nj][1] + bb.y);
            float x2 = gelu_fast(F.acc[mi][nj][2] + bb.x);
            float x3 = gelu_fast(F.acc[mi][nj][3] + bb.y);
            __half2 h01 = __floats2half2_rn(x0, x1);
            __half2 h23 = __floats2half2_rn(x2, x3);
            *(uint32_t*)(g_Hf + (size_t)row0 * 3072 + col) =
                *reinterpret_cast<uint32_t*>(&h01);
            *(uint32_t*)(g_Hf + (size_t)(row0 + 8) * 3072 + col) =
                *reinterpret_cast<uint32_t*>(&h23);
        }
    }
}

// ---------------------------------------------------------------------------
// GEMM2: out = H @ [W2 | We[idx]] + [b2 | be[idx]].  Grid (6, 256), 2 CTAs/SM.
// NC = 3072/64 = 48. B rows n<576 from W2t, n>=576 from Wet[e]; 128-row M
// tiles never straddle a batch (1024 rows / batch).
// ---------------------------------------------------------------------------
__global__ void __launch_bounds__(256, 2)
k_mm2(const float* __restrict__ b2, const float* __restrict__ be,
      const int* __restrict__ idx32, float* __restrict__ out)
{
    extern __shared__ char smem[];
    const uint32_t base = smem_u32(smem);
    const int tid = threadIdx.x, wid = tid >> 5, lane = tid & 31;
    const int bx = blockIdx.x, by = blockIdx.y;
    const int K = 3072, NC = 48;
    const int wm = wid & 3, wn = wid >> 2;
    const int e = load_expert_index(idx32, by >> 3);

    auto issue = [&](int c) {
        int st = (c % NSTAGES) * STAGE_BYTES;
        #pragma unroll
        for (int t = 0; t < 8; t++) {
            int idx = tid + t * 256;
            int region = idx >> 9;
            int w = idx & 511, r = w >> 2, ch = w & 3;
            int sub = region & 1;
            int isB = region >> 1;
            int p = ch ^ ((r >> 1) & 3);
            uint32_t sa = base + st + isB * 16384 + sub * 8192 + r * 64 + p * 16;
            const __half* src;
            size_t grow;
            if (!isB) {
                src = g_Hf;
                grow = (size_t)(by * 128 + r) * K;
            } else {
                int n = bx * 128 + r;
                if (n < 576) { src = g_W2t; grow = (size_t)n * K; }
                else { src = g_Wet; grow = ((size_t)e * 192 + (n - 576)) * K; }
            }
            cp16(sa, src + grow + c * 64 + sub * 32 + ch * 8);
        }
        CP_COMMIT();
    };

    Frags F;
    #pragma unroll
    for (int mi = 0; mi < 2; mi++)
        #pragma unroll
        for (int nj = 0; nj < 8; nj++)
            #pragma unroll
            for (int q = 0; q < 4; q++) F.acc[mi][nj][q] = 0.0f;

    issue(0); issue(1);
    for (int c = 0; c < NC; c++) {
        CP_WAIT(1);
        __syncthreads();
        if (c + 2 < NC) issue(c + 2); else CP_COMMIT();
        compute_chunk(base, (c % NSTAGES) * STAGE_BYTES, lane, wm, wn, F);
    }

    // epilogue: + bias (shared / expert), fp32 out [32768][768]
    const int g = lane >> 2, t4 = lane & 3;
    #pragma unroll
    for (int mi = 0; mi < 2; mi++) {
        #pragma unroll
        for (int nj = 0; nj < 8; nj++) {
            int row0 = by * 128 + wm * 32 + mi * 16 + g;
            int col  = bx * 128 + wn * 64 + nj * 8 + 2 * t4;
            float bx0, bx1;
            if (col < 576) { float2 bb = *(const float2*)(b2 + col); bx0 = bb.x; bx1 = bb.y; }
            else { float2 bb = *(const float2*)(be + e * 192 + (col - 576)); bx0 = bb.x; bx1 = bb.y; }
            float2 v0 = make_float2(F.acc[mi][nj][0] + bx0, F.acc[mi][nj][1] + bx1);
            float2 v1 = make_float2(F.acc[mi][nj][2] + bx0, F.acc[mi][nj][3] + bx1);
            *(float2*)(out + (size_t)row0 * 768 + col) = v0;
            *(float2*)(out + (size_t)(row0 + 8) * 768 + col) = v1;
        }
    }
}

// ---------------------------------------------------------------------------
extern "C" void kernel_launch(void* const* d_in, const int* in_sizes, int n_in,
                              void* d_out, int out_size)
{
    (void)in_sizes; (void)n_in; (void)out_size;
    const float* X   = (const float*)d_in[0];
    const int*   idx = (const int*)d_in[1];
    const float* W1  = (const float*)d_in[2];
    const float* b1  = (const float*)d_in[3];
    const float* W2  = (const float*)d_in[4];
    const float* b2  = (const float*)d_in[5];
    const float* We  = (const float*)d_in[6];
    const float* be  = (const float*)d_in[7];
    float* out = (float*)d_out;

    cudaFuncSetAttribute(k_mm1, cudaFuncAttributeMaxDynamicSharedMemorySize, SMEM_TOTAL);
    cudaFuncSetAttribute(k_mm2, cudaFuncAttributeMaxDynamicSharedMemorySize, SMEM_TOTAL);

    // fused prep: X convert + W1/W2/We transposes in one launch
    k_prep<<<24576 + 2304 + 1728 + 3456, 256>>>(X, W1, W2, We);

    k_mm1<<<dim3(3072 / 128, 32768 / 128), 256, SMEM_TOTAL>>>(b1);
    k_mm2<<<dim3(768 / 128, 32768 / 128), 256, SMEM_TOTAL>>>(b2, be, idx, out);
}